// round 2
// baseline (speedup 1.0000x reference)
#include <cuda_runtime.h>

#define NN   50000
#define NE   800000
#define FIN  128
#define FHID 128
#define FOUT 64

// ---------------- scratch (static __device__ -- no allocations) ----------------
static __device__ int   g_deg[NN];
static __device__ int   g_cur[NN];
static __device__ float g_dinv[NN];
static __device__ int   g_rowptr[NN + 1];
static __device__ int   g_col[NE];
static __device__ float g_h1[(size_t)NN * FHID];   // x@W1 (UNscaled)
static __device__ float g_h2[(size_t)NN * FHID];   // relu(layer1 out)
static __device__ float g_h2p[(size_t)NN * FOUT];  // dinv-scaled h2@W2

// ---------------- CSR build ----------------
__global__ void k_init() {
    int i = blockIdx.x * blockDim.x + threadIdx.x;
    if (i < NN) { g_deg[i] = 1; g_cur[i] = 0; }   // deg starts at 1 (self-loop)
}

__global__ void k_count(const int* __restrict__ ei) {
    int e4 = blockIdx.x * blockDim.x + threadIdx.x;
    if (e4 < NE / 4) {
        int4 d = reinterpret_cast<const int4*>(ei + NE)[e4];  // dst row
        atomicAdd(&g_deg[d.x], 1);
        atomicAdd(&g_deg[d.y], 1);
        atomicAdd(&g_deg[d.z], 1);
        atomicAdd(&g_deg[d.w], 1);
    }
}

// one-block, thread-coarsened scan: each thread owns a contiguous chunk.
// pass1: chunk sums -> block scan of 1024 totals -> pass2: write prefixes.
__global__ void __launch_bounds__(1024) k_scan() {
    const int C = (NN + 1023) / 1024;            // 49
    int t = threadIdx.x;
    int lane = t & 31, wid = t >> 5;
    int start = t * C;

    int s = 0;
    #pragma unroll 4
    for (int j = 0; j < C; j++) {
        int i = start + j;
        if (i < NN) s += g_deg[i] - 1;           // real in-edges only
    }

    // block exclusive scan of per-thread totals
    int x = s;
    #pragma unroll
    for (int o = 1; o < 32; o <<= 1) {
        int u = __shfl_up_sync(0xFFFFFFFFu, x, o);
        if (lane >= o) x += u;
    }
    __shared__ int wsum[32];
    if (lane == 31) wsum[wid] = x;
    __syncthreads();
    if (wid == 0) {
        int w = wsum[lane];
        #pragma unroll
        for (int o = 1; o < 32; o <<= 1) {
            int u = __shfl_up_sync(0xFFFFFFFFu, w, o);
            if (lane >= o) w += u;
        }
        wsum[lane] = w;
    }
    __syncthreads();
    int run = x - s + (wid > 0 ? wsum[wid - 1] : 0);   // exclusive prefix

    #pragma unroll 4
    for (int j = 0; j < C; j++) {
        int i = start + j;
        if (i < NN) {
            int d = g_deg[i];
            g_dinv[i] = rsqrtf((float)d);
            g_rowptr[i] = run;
            run += d - 1;
        }
    }
    if (t == 1023) g_rowptr[NN] = run;
}

__global__ void k_fill(const int* __restrict__ ei) {
    int e4 = blockIdx.x * blockDim.x + threadIdx.x;
    if (e4 < NE / 4) {
        int4 sv = reinterpret_cast<const int4*>(ei)[e4];       // src row
        int4 dv = reinterpret_cast<const int4*>(ei + NE)[e4];  // dst row
        int p;
        p = atomicAdd(&g_cur[dv.x], 1); g_col[g_rowptr[dv.x] + p] = sv.x;
        p = atomicAdd(&g_cur[dv.y], 1); g_col[g_rowptr[dv.y] + p] = sv.y;
        p = atomicAdd(&g_cur[dv.z], 1); g_col[g_rowptr[dv.z] + p] = sv.z;
        p = atomicAdd(&g_cur[dv.w], 1); g_col[g_rowptr[dv.w] + p] = sv.w;
    }
}

// ---------------- GEMM 1: g_h1 = x @ W1  (unscaled; dinv applied in agg1) ----------------
__global__ void __launch_bounds__(256) k_gemm1(const float* __restrict__ X,
                                               const float* __restrict__ W) {
    __shared__ float Xs[64][33];
    __shared__ float Ws[32][128];
    int tx = threadIdx.x;            // 0..31 -> 4 cols (float4)
    int ty = threadIdx.y;            // 0..7  -> 8 rows
    int tid = ty * 32 + tx;
    int row0 = blockIdx.x * 64;
    float4 acc[8];
    #pragma unroll
    for (int r = 0; r < 8; r++) acc[r] = make_float4(0.f, 0.f, 0.f, 0.f);

    for (int k0 = 0; k0 < FIN; k0 += 32) {
        #pragma unroll
        for (int t = tid; t < 64 * 32; t += 256) {
            int r = t >> 5, c = t & 31;
            int row = row0 + r;
            Xs[r][c] = (row < NN) ? X[(size_t)row * FIN + k0 + c] : 0.f;
        }
        #pragma unroll
        for (int t = tid; t < 1024; t += 256) {    // 32x128 floats as float4
            int r = t >> 5, c = t & 31;
            reinterpret_cast<float4*>(&Ws[r][0])[c] =
                reinterpret_cast<const float4*>(&W[(size_t)(k0 + r) * FHID])[c];
        }
        __syncthreads();
        #pragma unroll
        for (int kk = 0; kk < 32; kk++) {
            float4 w = reinterpret_cast<float4*>(&Ws[kk][0])[tx];
            #pragma unroll
            for (int r = 0; r < 8; r++) {
                float xv = Xs[ty * 8 + r][kk];
                acc[r].x += xv * w.x; acc[r].y += xv * w.y;
                acc[r].z += xv * w.z; acc[r].w += xv * w.w;
            }
        }
        __syncthreads();
    }
    #pragma unroll
    for (int r = 0; r < 8; r++) {
        int row = row0 + ty * 8 + r;
        if (row < NN)
            reinterpret_cast<float4*>(&g_h1[(size_t)row * FHID])[tx] = acc[r];
    }
}

// ---------------- AGG 1: g_h2[i] = relu(dinv[i]*(sum_s dinv[s]*h1[s] + dinv[i]*h1[i]) + b1) ----------------
__global__ void __launch_bounds__(256) k_agg1(const float* __restrict__ b1) {
    int gw   = (blockIdx.x * 256 + threadIdx.x) >> 5;   // node = warp id
    int lane = threadIdx.x & 31;
    if (gw >= NN) return;
    const float4* h = reinterpret_cast<const float4*>(g_h1);
    float dv = g_dinv[gw];
    float4 self = h[(size_t)gw * 32 + lane];
    float4 acc;
    acc.x = self.x * dv; acc.y = self.y * dv;
    acc.z = self.z * dv; acc.w = self.w * dv;

    int s0 = g_rowptr[gw], s1 = g_rowptr[gw + 1];
    int j = s0;
    for (; j + 1 < s1; j += 2) {
        int sA = __ldg(&g_col[j]);
        int sB = __ldg(&g_col[j + 1]);
        float dA = __ldg(&g_dinv[sA]);
        float dB = __ldg(&g_dinv[sB]);
        float4 a = h[(size_t)sA * 32 + lane];
        float4 b = h[(size_t)sB * 32 + lane];
        acc.x += a.x * dA + b.x * dB;
        acc.y += a.y * dA + b.y * dB;
        acc.z += a.z * dA + b.z * dB;
        acc.w += a.w * dA + b.w * dB;
    }
    if (j < s1) {
        int sA = __ldg(&g_col[j]);
        float dA = __ldg(&g_dinv[sA]);
        float4 a = h[(size_t)sA * 32 + lane];
        acc.x += a.x * dA; acc.y += a.y * dA;
        acc.z += a.z * dA; acc.w += a.w * dA;
    }
    float4 bb = reinterpret_cast<const float4*>(b1)[lane];
    float4 z;
    z.x = fmaxf(acc.x * dv + bb.x, 0.f);
    z.y = fmaxf(acc.y * dv + bb.y, 0.f);
    z.z = fmaxf(acc.z * dv + bb.z, 0.f);
    z.w = fmaxf(acc.w * dv + bb.w, 0.f);
    reinterpret_cast<float4*>(g_h2)[(size_t)gw * 32 + lane] = z;
}

// ---------------- GEMM 2: g_h2p[i] = dinv[i] * (g_h2 @ W2)[i]  (128x64) ----------------
__global__ void __launch_bounds__(256) k_gemm2(const float* __restrict__ W) {
    __shared__ float Xs[64][33];
    __shared__ float Ws[32][64];
    int tid = threadIdx.x;
    int tx = tid & 15;               // 0..15 -> 4 cols (float4), 64 cols total
    int ty = tid >> 4;               // 0..15 -> 4 rows
    int row0 = blockIdx.x * 64;
    float4 acc[4];
    #pragma unroll
    for (int r = 0; r < 4; r++) acc[r] = make_float4(0.f, 0.f, 0.f, 0.f);

    for (int k0 = 0; k0 < FHID; k0 += 32) {
        #pragma unroll
        for (int t = tid; t < 64 * 32; t += 256) {
            int r = t >> 5, c = t & 31;
            int row = row0 + r;
            Xs[r][c] = (row < NN) ? g_h2[(size_t)row * FHID + k0 + c] : 0.f;
        }
        #pragma unroll
        for (int t = tid; t < 512; t += 256) {     // 32x64 floats as float4
            int r = t >> 4, c = t & 15;
            reinterpret_cast<float4*>(&Ws[r][0])[c] =
                reinterpret_cast<const float4*>(&W[(size_t)(k0 + r) * FOUT])[c];
        }
        __syncthreads();
        #pragma unroll
        for (int kk = 0; kk < 32; kk++) {
            float4 w = reinterpret_cast<float4*>(&Ws[kk][0])[tx];
            #pragma unroll
            for (int r = 0; r < 4; r++) {
                float xv = Xs[ty * 4 + r][kk];
                acc[r].x += xv * w.x; acc[r].y += xv * w.y;
                acc[r].z += xv * w.z; acc[r].w += xv * w.w;
            }
        }
        __syncthreads();
    }
    #pragma unroll
    for (int r = 0; r < 4; r++) {
        int row = row0 + ty * 4 + r;
        if (row < NN) {
            float s = g_dinv[row];
            float4 v = acc[r];
            v.x *= s; v.y *= s; v.z *= s; v.w *= s;
            reinterpret_cast<float4*>(&g_h2p[(size_t)row * FOUT])[tx] = v;
        }
    }
}

// ---------------- AGG 2: out[i] = dinv[i]*(sum_nb g_h2p + g_h2p[i]) + b2 ----------------
__global__ void __launch_bounds__(256) k_agg2(const float* __restrict__ b2,
                                              float* __restrict__ out) {
    int gw   = (blockIdx.x * 256 + threadIdx.x) >> 5;
    int lane = threadIdx.x & 31;
    if (gw >= NN) return;
    const float2* h = reinterpret_cast<const float2*>(g_h2p);
    float2 acc = h[(size_t)gw * 32 + lane];             // self-loop term (already dinv-scaled)
    int s0 = g_rowptr[gw], s1 = g_rowptr[gw + 1];
    int j = s0;
    for (; j + 1 < s1; j += 2) {
        int sA = __ldg(&g_col[j]);
        int sB = __ldg(&g_col[j + 1]);
        float2 a = h[(size_t)sA * 32 + lane];
        float2 b = h[(size_t)sB * 32 + lane];
        acc.x += a.x + b.x;
        acc.y += a.y + b.y;
    }
    if (j < s1) {
        int sA = __ldg(&g_col[j]);
        float2 a = h[(size_t)sA * 32 + lane];
        acc.x += a.x; acc.y += a.y;
    }
    float dv = g_dinv[gw];
    float2 bb = reinterpret_cast<const float2*>(b2)[lane];
    float2 z;
    z.x = acc.x * dv + bb.x;
    z.y = acc.y * dv + bb.y;
    reinterpret_cast<float2*>(out)[(size_t)gw * 32 + lane] = z;
}

// ---------------- launch ----------------
extern "C" void kernel_launch(void* const* d_in, const int* in_sizes, int n_in,
                              void* d_out, int out_size) {
    const float* x  = (const float*)d_in[0];
    const int*   ei = (const int*)d_in[1];
    const float* W1 = (const float*)d_in[2];
    const float* b1 = (const float*)d_in[3];
    const float* W2 = (const float*)d_in[4];
    const float* b2 = (const float*)d_in[5];
    float* out = (float*)d_out;

    // one-time stream/event setup (host-side only, happens on the un-captured
    // correctness call; enqueued work is identical every call)
    static cudaStream_t s_side = nullptr;
    static cudaEvent_t  ev_fork = nullptr, ev_join = nullptr;
    if (!s_side) {
        cudaStreamCreateWithFlags(&s_side, cudaStreamNonBlocking);
        cudaEventCreateWithFlags(&ev_fork, cudaEventDisableTiming);
        cudaEventCreateWithFlags(&ev_join, cudaEventDisableTiming);
    }

    // fork: CSR build on side stream, gemm1 on main stream (independent)
    cudaEventRecord(ev_fork, 0);
    cudaStreamWaitEvent(s_side, ev_fork, 0);

    k_init <<<(NN + 255) / 256, 256, 0, s_side>>>();
    k_count<<<(NE / 4 + 255) / 256, 256, 0, s_side>>>(ei);
    k_scan <<<1, 1024, 0, s_side>>>();
    k_fill <<<(NE / 4 + 255) / 256, 256, 0, s_side>>>(ei);
    cudaEventRecord(ev_join, s_side);

    k_gemm1<<<(NN + 63) / 64, dim3(32, 8)>>>(x, W1);

    // join: agg1 needs h1 + CSR + dinv
    cudaStreamWaitEvent(0, ev_join, 0);
    k_agg1 <<<(NN * 32 + 255) / 256, 256>>>(b1);
    k_gemm2<<<(NN + 63) / 64, 256>>>(W2);
    k_agg2 <<<(NN * 32 + 255) / 256, 256>>>(b2, out);
}

// round 3
// speedup vs baseline: 1.0385x; 1.0385x over previous
#include <cuda_runtime.h>
#include <cuda_fp16.h>

#define NN   50000
#define NE   800000
#define FIN  128
#define FHID 128
#define FOUT 64

// ---------------- scratch (static __device__ -- no allocations) ----------------
static __device__ int   g_deg[NN];
static __device__ int   g_cur[NN];
static __device__ float g_dinv[NN];
static __device__ int   g_rowptr[NN + 1];
static __device__ int   g_col[NE];
static __device__ __align__(16) __half g_h1h[(size_t)NN * FHID];  // dinv*(x@W1), fp16
static __device__ float g_h2[(size_t)NN * FHID];                   // relu(layer1 out), fp32
static __device__ __align__(16) __half g_h2p[(size_t)NN * FOUT];   // dinv*(h2@W2), fp16

// ---------------- CSR build ----------------
__global__ void k_init() {
    int i = blockIdx.x * blockDim.x + threadIdx.x;
    if (i < NN) { g_deg[i] = 1; g_cur[i] = 0; }   // deg starts at 1 (self-loop)
}

__global__ void k_count(const int* __restrict__ ei) {
    int e = blockIdx.x * blockDim.x + threadIdx.x;
    if (e < NE) atomicAdd(&g_deg[ei[NE + e]], 1);  // dst = row 1
}

// one-block, thread-coarsened scan: each thread owns a contiguous chunk.
__global__ void __launch_bounds__(1024) k_scan() {
    const int C = (NN + 1023) / 1024;            // 49
    int t = threadIdx.x;
    int lane = t & 31, wid = t >> 5;
    int start = t * C;

    int s = 0;
    #pragma unroll 4
    for (int j = 0; j < C; j++) {
        int i = start + j;
        if (i < NN) s += g_deg[i] - 1;           // real in-edges only
    }

    int x = s;
    #pragma unroll
    for (int o = 1; o < 32; o <<= 1) {
        int u = __shfl_up_sync(0xFFFFFFFFu, x, o);
        if (lane >= o) x += u;
    }
    __shared__ int wsum[32];
    if (lane == 31) wsum[wid] = x;
    __syncthreads();
    if (wid == 0) {
        int w = wsum[lane];
        #pragma unroll
        for (int o = 1; o < 32; o <<= 1) {
            int u = __shfl_up_sync(0xFFFFFFFFu, w, o);
            if (lane >= o) w += u;
        }
        wsum[lane] = w;
    }
    __syncthreads();
    int run = x - s + (wid > 0 ? wsum[wid - 1] : 0);

    #pragma unroll 4
    for (int j = 0; j < C; j++) {
        int i = start + j;
        if (i < NN) {
            int d = g_deg[i];
            g_dinv[i] = rsqrtf((float)d);
            g_rowptr[i] = run;
            run += d - 1;
        }
    }
    if (t == 1023) g_rowptr[NN] = run;
}

__global__ void k_fill(const int* __restrict__ ei) {
    int e = blockIdx.x * blockDim.x + threadIdx.x;
    if (e < NE) {
        int d = ei[NE + e];
        int p = atomicAdd(&g_cur[d], 1);
        g_col[g_rowptr[d] + p] = ei[e];            // src = row 0
    }
}

// ---------------- GEMM 1: g_h1h[i] = fp16( dinv[i] * (x @ W1)[i] ) ----------------
__global__ void __launch_bounds__(256) k_gemm1(const float* __restrict__ X,
                                               const float* __restrict__ W) {
    __shared__ float Xs[64][33];
    __shared__ float Ws[32][128];
    int tx = threadIdx.x;            // 0..31 -> 4 cols
    int ty = threadIdx.y;            // 0..7  -> 8 rows
    int tid = ty * 32 + tx;
    int row0 = blockIdx.x * 64;
    float4 acc[8];
    #pragma unroll
    for (int r = 0; r < 8; r++) acc[r] = make_float4(0.f, 0.f, 0.f, 0.f);

    for (int k0 = 0; k0 < FIN; k0 += 32) {
        #pragma unroll
        for (int t = tid; t < 64 * 32; t += 256) {
            int r = t >> 5, c = t & 31;
            int row = row0 + r;
            Xs[r][c] = (row < NN) ? X[(size_t)row * FIN + k0 + c] : 0.f;
        }
        #pragma unroll
        for (int t = tid; t < 1024; t += 256) {
            int r = t >> 5, c = t & 31;
            reinterpret_cast<float4*>(&Ws[r][0])[c] =
                reinterpret_cast<const float4*>(&W[(size_t)(k0 + r) * FHID])[c];
        }
        __syncthreads();
        #pragma unroll
        for (int kk = 0; kk < 32; kk++) {
            float4 w = reinterpret_cast<float4*>(&Ws[kk][0])[tx];
            #pragma unroll
            for (int r = 0; r < 8; r++) {
                float xv = Xs[ty * 8 + r][kk];
                acc[r].x += xv * w.x; acc[r].y += xv * w.y;
                acc[r].z += xv * w.z; acc[r].w += xv * w.w;
            }
        }
        __syncthreads();
    }
    #pragma unroll
    for (int r = 0; r < 8; r++) {
        int row = row0 + ty * 8 + r;
        if (row < NN) {
            float s = g_dinv[row];
            __half2 lo = __floats2half2_rn(acc[r].x * s, acc[r].y * s);
            __half2 hi = __floats2half2_rn(acc[r].z * s, acc[r].w * s);
            uint2 packed;
            packed.x = *reinterpret_cast<unsigned*>(&lo);
            packed.y = *reinterpret_cast<unsigned*>(&hi);
            reinterpret_cast<uint2*>(g_h1h)[(size_t)row * 32 + tx] = packed;
        }
    }
}

// ---------------- AGG 1: g_h2[i] = relu(dinv[i]*(sum_nb h1 + h1[i]) + b1) ----------------
__device__ __forceinline__ void acc_row16(float4& acc, uint2 raw) {
    __half2 h01 = *reinterpret_cast<__half2*>(&raw.x);
    __half2 h23 = *reinterpret_cast<__half2*>(&raw.y);
    float2 f01 = __half22float2(h01);
    float2 f23 = __half22float2(h23);
    acc.x += f01.x; acc.y += f01.y; acc.z += f23.x; acc.w += f23.y;
}

__global__ void __launch_bounds__(256) k_agg1(const float* __restrict__ b1) {
    int gw   = (blockIdx.x * 256 + threadIdx.x) >> 5;   // node = warp id
    int lane = threadIdx.x & 31;
    if (gw >= NN) return;
    const uint2* h = reinterpret_cast<const uint2*>(g_h1h);
    float4 acc = make_float4(0.f, 0.f, 0.f, 0.f);
    acc_row16(acc, h[(size_t)gw * 32 + lane]);          // self-loop term

    int s0 = g_rowptr[gw], s1 = g_rowptr[gw + 1];
    int j = s0;
    for (; j + 1 < s1; j += 2) {
        int sA = __ldg(&g_col[j]);
        int sB = __ldg(&g_col[j + 1]);
        uint2 a = __ldg(&h[(size_t)sA * 32 + lane]);
        uint2 b = __ldg(&h[(size_t)sB * 32 + lane]);
        acc_row16(acc, a);
        acc_row16(acc, b);
    }
    if (j < s1) {
        int sA = __ldg(&g_col[j]);
        acc_row16(acc, __ldg(&h[(size_t)sA * 32 + lane]));
    }
    float dv = g_dinv[gw];
    float4 bb = reinterpret_cast<const float4*>(b1)[lane];
    float4 z;
    z.x = fmaxf(acc.x * dv + bb.x, 0.f);
    z.y = fmaxf(acc.y * dv + bb.y, 0.f);
    z.z = fmaxf(acc.z * dv + bb.z, 0.f);
    z.w = fmaxf(acc.w * dv + bb.w, 0.f);
    reinterpret_cast<float4*>(g_h2)[(size_t)gw * 32 + lane] = z;
}

// ---------------- GEMM 2: g_h2p[i] = fp16( dinv[i] * (g_h2 @ W2)[i] ) ----------------
__global__ void __launch_bounds__(256) k_gemm2(const float* __restrict__ W) {
    __shared__ float Xs[64][33];
    __shared__ float Ws[32][64];
    int tid = threadIdx.x;
    int tx = tid & 15;               // 0..15 -> 4 cols
    int ty = tid >> 4;               // 0..15 -> 4 rows
    int row0 = blockIdx.x * 64;
    float4 acc[4];
    #pragma unroll
    for (int r = 0; r < 4; r++) acc[r] = make_float4(0.f, 0.f, 0.f, 0.f);

    for (int k0 = 0; k0 < FHID; k0 += 32) {
        #pragma unroll
        for (int t = tid; t < 64 * 32; t += 256) {
            int r = t >> 5, c = t & 31;
            int row = row0 + r;
            Xs[r][c] = (row < NN) ? g_h2[(size_t)row * FHID + k0 + c] : 0.f;
        }
        #pragma unroll
        for (int t = tid; t < 512; t += 256) {
            int r = t >> 4, c = t & 15;
            reinterpret_cast<float4*>(&Ws[r][0])[c] =
                reinterpret_cast<const float4*>(&W[(size_t)(k0 + r) * FOUT])[c];
        }
        __syncthreads();
        #pragma unroll
        for (int kk = 0; kk < 32; kk++) {
            float4 w = reinterpret_cast<float4*>(&Ws[kk][0])[tx];
            #pragma unroll
            for (int r = 0; r < 4; r++) {
                float xv = Xs[ty * 4 + r][kk];
                acc[r].x += xv * w.x; acc[r].y += xv * w.y;
                acc[r].z += xv * w.z; acc[r].w += xv * w.w;
            }
        }
        __syncthreads();
    }
    #pragma unroll
    for (int r = 0; r < 4; r++) {
        int row = row0 + ty * 4 + r;
        if (row < NN) {
            float s = g_dinv[row];
            __half2 lo = __floats2half2_rn(acc[r].x * s, acc[r].y * s);
            __half2 hi = __floats2half2_rn(acc[r].z * s, acc[r].w * s);
            uint2 packed;
            packed.x = *reinterpret_cast<unsigned*>(&lo);
            packed.y = *reinterpret_cast<unsigned*>(&hi);
            reinterpret_cast<uint2*>(g_h2p)[(size_t)row * 16 + tx] = packed;
        }
    }
}

// ---------------- AGG 2: out[i] = dinv[i]*(sum_nb h2p + h2p[i]) + b2 ----------------
__global__ void __launch_bounds__(256) k_agg2(const float* __restrict__ b2,
                                              float* __restrict__ out) {
    int gw   = (blockIdx.x * 256 + threadIdx.x) >> 5;
    int lane = threadIdx.x & 31;
    if (gw >= NN) return;
    const __half2* h = reinterpret_cast<const __half2*>(g_h2p);
    float2 acc;
    {
        float2 v = __half22float2(h[(size_t)gw * 32 + lane]);  // self-loop
        acc.x = v.x; acc.y = v.y;
    }
    int s0 = g_rowptr[gw], s1 = g_rowptr[gw + 1];
    int j = s0;
    for (; j + 1 < s1; j += 2) {
        int sA = __ldg(&g_col[j]);
        int sB = __ldg(&g_col[j + 1]);
        float2 a = __half22float2(__ldg(&h[(size_t)sA * 32 + lane]));
        float2 b = __half22float2(__ldg(&h[(size_t)sB * 32 + lane]));
        acc.x += a.x + b.x;
        acc.y += a.y + b.y;
    }
    if (j < s1) {
        int sA = __ldg(&g_col[j]);
        float2 a = __half22float2(__ldg(&h[(size_t)sA * 32 + lane]));
        acc.x += a.x; acc.y += a.y;
    }
    float dv = g_dinv[gw];
    float2 bb = reinterpret_cast<const float2*>(b2)[lane];
    float2 z;
    z.x = acc.x * dv + bb.x;
    z.y = acc.y * dv + bb.y;
    reinterpret_cast<float2*>(out)[(size_t)gw * 32 + lane] = z;
}

// ---------------- launch (sequential, single stream) ----------------
extern "C" void kernel_launch(void* const* d_in, const int* in_sizes, int n_in,
                              void* d_out, int out_size) {
    const float* x  = (const float*)d_in[0];
    const int*   ei = (const int*)d_in[1];
    const float* W1 = (const float*)d_in[2];
    const float* b1 = (const float*)d_in[3];
    const float* W2 = (const float*)d_in[4];
    const float* b2 = (const float*)d_in[5];
    float* out = (float*)d_out;

    k_init <<<(NN + 255) / 256, 256>>>();
    k_count<<<(NE + 255) / 256, 256>>>(ei);
    k_scan <<<1, 1024>>>();
    k_fill <<<(NE + 255) / 256, 256>>>(ei);
    k_gemm1<<<(NN + 63) / 64, dim3(32, 8)>>>(x, W1);
    k_agg1 <<<(NN * 32 + 255) / 256, 256>>>(b1);
    k_gemm2<<<(NN + 63) / 64, 256>>>(W2);
    k_agg2 <<<(NN * 32 + 255) / 256, 256>>>(b2, out);
}

// round 4
// speedup vs baseline: 1.5760x; 1.5176x over previous
#include <cuda_runtime.h>
#include <cuda_fp16.h>
#include <cstdint>

#define NN   50000
#define NE   800000
#define FIN  128
#define FHID 128
#define FOUT 64

// ---------------- scratch (static __device__ -- no allocations) ----------------
static __device__ int   g_deg[NN];
static __device__ int   g_cur[NN];
static __device__ float g_dinv[NN];
static __device__ int   g_rowptr[NN + 1];
static __device__ int   g_col[NE];
static __device__ __align__(16) __half g_w1h[FIN * FHID];
static __device__ __align__(16) __half g_w2h[FHID * FOUT];
static __device__ __align__(16) __half g_h1h[(size_t)NN * FHID];  // dinv*(x@W1)
static __device__ __align__(16) __half g_h2h[(size_t)NN * FHID];  // relu(layer1)
static __device__ __align__(16) __half g_h2p[(size_t)NN * FOUT];  // dinv*(h2@W2)

// ---------------- mma helpers ----------------
__device__ __forceinline__ uint32_t cvta_s(const void* p) {
    return (uint32_t)__cvta_generic_to_shared(p);
}
__device__ __forceinline__ void ldmA(uint32_t& a0, uint32_t& a1, uint32_t& a2,
                                     uint32_t& a3, uint32_t addr) {
    asm volatile("ldmatrix.sync.aligned.m8n8.x4.shared.b16 {%0,%1,%2,%3}, [%4];\n"
                 : "=r"(a0), "=r"(a1), "=r"(a2), "=r"(a3) : "r"(addr));
}
__device__ __forceinline__ void ldmBT(uint32_t& b0, uint32_t& b1, uint32_t& b2,
                                      uint32_t& b3, uint32_t addr) {
    asm volatile("ldmatrix.sync.aligned.m8n8.x4.trans.shared.b16 {%0,%1,%2,%3}, [%4];\n"
                 : "=r"(b0), "=r"(b1), "=r"(b2), "=r"(b3) : "r"(addr));
}
__device__ __forceinline__ void mma16816(float* d, uint32_t a0, uint32_t a1,
                                         uint32_t a2, uint32_t a3,
                                         uint32_t b0, uint32_t b1) {
    asm volatile("mma.sync.aligned.m16n8k16.row.col.f32.f16.f16.f32 "
                 "{%0,%1,%2,%3}, {%4,%5,%6,%7}, {%8,%9}, {%0,%1,%2,%3};\n"
                 : "+f"(d[0]), "+f"(d[1]), "+f"(d[2]), "+f"(d[3])
                 : "r"(a0), "r"(a1), "r"(a2), "r"(a3), "r"(b0), "r"(b1));
}

// ---------------- CSR build ----------------
__global__ void k_init() {
    int i = blockIdx.x * blockDim.x + threadIdx.x;
    if (i < NN) { g_deg[i] = 1; g_cur[i] = 0; }   // deg starts at 1 (self-loop)
}

__global__ void k_count(const int* __restrict__ ei) {
    int e = blockIdx.x * blockDim.x + threadIdx.x;
    if (e < NE / 2) {
        int d0 = ei[NE + e];
        int d1 = ei[NE + e + NE / 2];
        atomicAdd(&g_deg[d0], 1);
        atomicAdd(&g_deg[d1], 1);
    }
}

__global__ void __launch_bounds__(1024) k_scan() {
    const int C = (NN + 1023) / 1024;            // 49
    int t = threadIdx.x;
    int lane = t & 31, wid = t >> 5;
    int start = t * C;

    int s = 0;
    #pragma unroll 4
    for (int j = 0; j < C; j++) {
        int i = start + j;
        if (i < NN) s += g_deg[i] - 1;
    }
    int x = s;
    #pragma unroll
    for (int o = 1; o < 32; o <<= 1) {
        int u = __shfl_up_sync(0xFFFFFFFFu, x, o);
        if (lane >= o) x += u;
    }
    __shared__ int wsum[32];
    if (lane == 31) wsum[wid] = x;
    __syncthreads();
    if (wid == 0) {
        int w = wsum[lane];
        #pragma unroll
        for (int o = 1; o < 32; o <<= 1) {
            int u = __shfl_up_sync(0xFFFFFFFFu, w, o);
            if (lane >= o) w += u;
        }
        wsum[lane] = w;
    }
    __syncthreads();
    int run = x - s + (wid > 0 ? wsum[wid - 1] : 0);
    #pragma unroll 4
    for (int j = 0; j < C; j++) {
        int i = start + j;
        if (i < NN) {
            int d = g_deg[i];
            g_dinv[i] = rsqrtf((float)d);
            g_rowptr[i] = run;
            run += d - 1;
        }
    }
    if (t == 1023) g_rowptr[NN] = run;
}

__global__ void k_fill(const int* __restrict__ ei) {
    int e = blockIdx.x * blockDim.x + threadIdx.x;
    if (e < NE / 2) {
        int d0 = ei[NE + e];
        int s0 = ei[e];
        int d1 = ei[NE + e + NE / 2];
        int s1 = ei[e + NE / 2];
        int p0 = atomicAdd(&g_cur[d0], 1);
        int p1 = atomicAdd(&g_cur[d1], 1);
        g_col[g_rowptr[d0] + p0] = s0;
        g_col[g_rowptr[d1] + p1] = s1;
    }
}

// ---------------- W fp32 -> fp16 ----------------
__global__ void k_convW(const float* __restrict__ W1, const float* __restrict__ W2) {
    int i = blockIdx.x * blockDim.x + threadIdx.x;
    if (i < FIN * FHID) g_w1h[i] = __float2half(W1[i]);
    else if (i < FIN * FHID + FHID * FOUT) g_w2h[i - FIN * FHID] = __float2half(W2[i - FIN * FHID]);
}

// ---------------- GEMM 1 (tensor core): g_h1h = fp16(dinv * (x @ W1)) ----------------
// block = 64 rows, full N=128; K split in 2 chunks of 64.
__global__ void __launch_bounds__(256) k_gemm1(const float* __restrict__ X) {
    __shared__ __half As[64][72];     // 64x64 fp16 (padded: 36 words/row)
    __shared__ __half Bs[64][136];    // 64x128 fp16 (padded: 68 words/row)
    int tid = threadIdx.x;
    int row0 = blockIdx.x * 64;
    int wid = tid >> 5, lane = tid & 31;
    int rw = (wid & 3) * 16;          // warp row in tile
    int cw = (wid >> 2) * 64;         // warp col
    float acc[8][4] = {};

    #pragma unroll
    for (int kb = 0; kb < 2; kb++) {
        // X tile: 64 rows x 64 cols fp32 -> fp16 (1024 float4)
        #pragma unroll
        for (int i = 0; i < 4; i++) {
            int idx = tid + i * 256;
            int r = idx >> 4, c4 = idx & 15;
            int row = row0 + r;
            float4 v = (row < NN)
                ? reinterpret_cast<const float4*>(X)[(size_t)row * 32 + kb * 16 + c4]
                : make_float4(0.f, 0.f, 0.f, 0.f);
            __half2 lo = __floats2half2_rn(v.x, v.y);
            __half2 hi = __floats2half2_rn(v.z, v.w);
            *reinterpret_cast<__half2*>(&As[r][c4 * 4])     = lo;
            *reinterpret_cast<__half2*>(&As[r][c4 * 4 + 2]) = hi;
        }
        // W tile: 64 rows x 128 cols fp16 (2048 uint2)
        #pragma unroll
        for (int i = 0; i < 8; i++) {
            int idx = tid + i * 256;
            int r = idx >> 5, c = idx & 31;
            uint2 w = reinterpret_cast<const uint2*>(g_w1h)[(size_t)(kb * 64 + r) * 32 + c];
            *reinterpret_cast<uint2*>(&Bs[r][c * 4]) = w;
        }
        __syncthreads();
        #pragma unroll
        for (int k = 0; k < 4; k++) {
            int k0 = k * 16;
            uint32_t a0, a1, a2, a3;
            ldmA(a0, a1, a2, a3, cvta_s(&As[rw + (lane & 15)][k0 + (lane >> 4) * 8]));
            #pragma unroll
            for (int nn = 0; nn < 8; nn += 2) {
                uint32_t b0, b1, b2, b3;
                ldmBT(b0, b1, b2, b3,
                      cvta_s(&Bs[k0 + (lane & 15)][cw + nn * 8 + (lane >> 4) * 8]));
                mma16816(acc[nn],     a0, a1, a2, a3, b0, b1);
                mma16816(acc[nn + 1], a0, a1, a2, a3, b2, b3);
            }
        }
        __syncthreads();
    }
    // epilogue: * dinv, -> fp16
    int g  = lane >> 2, cq = (lane & 3) * 2;
    int ra = row0 + rw + g, rb = ra + 8;
    float da = (ra < NN) ? g_dinv[ra] : 0.f;
    float db = (rb < NN) ? g_dinv[rb] : 0.f;
    #pragma unroll
    for (int nn = 0; nn < 8; nn++) {
        int col = cw + nn * 8 + cq;
        if (ra < NN)
            *reinterpret_cast<__half2*>(&g_h1h[(size_t)ra * FHID + col]) =
                __floats2half2_rn(acc[nn][0] * da, acc[nn][1] * da);
        if (rb < NN)
            *reinterpret_cast<__half2*>(&g_h1h[(size_t)rb * FHID + col]) =
                __floats2half2_rn(acc[nn][2] * db, acc[nn][3] * db);
    }
}

// ---------------- AGG 1: g_h2h[i] = fp16(relu(dinv[i]*(sum_nb h1 + h1[i]) + b1)) ----------------
__device__ __forceinline__ void acc_row16(float4& acc, uint2 raw) {
    float2 f01 = __half22float2(*reinterpret_cast<__half2*>(&raw.x));
    float2 f23 = __half22float2(*reinterpret_cast<__half2*>(&raw.y));
    acc.x += f01.x; acc.y += f01.y; acc.z += f23.x; acc.w += f23.y;
}

__global__ void __launch_bounds__(256) k_agg1(const float* __restrict__ b1) {
    int gw   = (blockIdx.x * 256 + threadIdx.x) >> 5;
    int lane = threadIdx.x & 31;
    if (gw >= NN) return;
    const uint2* h = reinterpret_cast<const uint2*>(g_h1h);
    float4 acc = make_float4(0.f, 0.f, 0.f, 0.f);
    acc_row16(acc, h[(size_t)gw * 32 + lane]);          // self-loop

    int s0 = g_rowptr[gw], s1 = g_rowptr[gw + 1];
    int j = s0;
    for (; j + 1 < s1; j += 2) {
        int sA = __ldg(&g_col[j]);
        int sB = __ldg(&g_col[j + 1]);
        uint2 a = __ldg(&h[(size_t)sA * 32 + lane]);
        uint2 b = __ldg(&h[(size_t)sB * 32 + lane]);
        acc_row16(acc, a);
        acc_row16(acc, b);
    }
    if (j < s1) {
        int sA = __ldg(&g_col[j]);
        acc_row16(acc, __ldg(&h[(size_t)sA * 32 + lane]));
    }
    float dv = g_dinv[gw];
    float4 bb = reinterpret_cast<const float4*>(b1)[lane];
    float zx = fmaxf(acc.x * dv + bb.x, 0.f);
    float zy = fmaxf(acc.y * dv + bb.y, 0.f);
    float zz = fmaxf(acc.z * dv + bb.z, 0.f);
    float zw = fmaxf(acc.w * dv + bb.w, 0.f);
    uint2 packed;
    __half2 lo = __floats2half2_rn(zx, zy);
    __half2 hi = __floats2half2_rn(zz, zw);
    packed.x = *reinterpret_cast<unsigned*>(&lo);
    packed.y = *reinterpret_cast<unsigned*>(&hi);
    reinterpret_cast<uint2*>(g_h2h)[(size_t)gw * 32 + lane] = packed;
}

// ---------------- GEMM 2 (tensor core): g_h2p = fp16(dinv * (h2 @ W2)), N=64 ----------------
__global__ void __launch_bounds__(256) k_gemm2() {
    __shared__ __half As[64][72];     // 64x64
    __shared__ __half Bs[64][72];     // 64x64
    int tid = threadIdx.x;
    int row0 = blockIdx.x * 64;
    int wid = tid >> 5, lane = tid & 31;
    int rw = (wid & 3) * 16;
    int cw = (wid >> 2) * 32;
    float acc[4][4] = {};

    #pragma unroll
    for (int kb = 0; kb < 2; kb++) {
        // h2 tile: 64 rows x 64 cols fp16 (1024 uint2)
        #pragma unroll
        for (int i = 0; i < 4; i++) {
            int idx = tid + i * 256;
            int r = idx >> 4, c = idx & 15;
            int row = row0 + r;
            uint2 v = (row < NN)
                ? reinterpret_cast<const uint2*>(g_h2h + (size_t)row * FHID + kb * 64)[c]
                : make_uint2(0u, 0u);
            *reinterpret_cast<uint2*>(&As[r][c * 4]) = v;
        }
        // W2 tile: 64 rows x 64 cols fp16 (1024 uint2)
        #pragma unroll
        for (int i = 0; i < 4; i++) {
            int idx = tid + i * 256;
            int r = idx >> 4, c = idx & 15;
            uint2 w = reinterpret_cast<const uint2*>(g_w2h)[(size_t)(kb * 64 + r) * 16 + c];
            *reinterpret_cast<uint2*>(&Bs[r][c * 4]) = w;
        }
        __syncthreads();
        #pragma unroll
        for (int k = 0; k < 4; k++) {
            int k0 = k * 16;
            uint32_t a0, a1, a2, a3;
            ldmA(a0, a1, a2, a3, cvta_s(&As[rw + (lane & 15)][k0 + (lane >> 4) * 8]));
            #pragma unroll
            for (int nn = 0; nn < 4; nn += 2) {
                uint32_t b0, b1, b2, b3;
                ldmBT(b0, b1, b2, b3,
                      cvta_s(&Bs[k0 + (lane & 15)][cw + nn * 8 + (lane >> 4) * 8]));
                mma16816(acc[nn],     a0, a1, a2, a3, b0, b1);
                mma16816(acc[nn + 1], a0, a1, a2, a3, b2, b3);
            }
        }
        __syncthreads();
    }
    int g  = lane >> 2, cq = (lane & 3) * 2;
    int ra = row0 + rw + g, rb = ra + 8;
    float da = (ra < NN) ? g_dinv[ra] : 0.f;
    float db = (rb < NN) ? g_dinv[rb] : 0.f;
    #pragma unroll
    for (int nn = 0; nn < 4; nn++) {
        int col = cw + nn * 8 + cq;
        if (ra < NN)
            *reinterpret_cast<__half2*>(&g_h2p[(size_t)ra * FOUT + col]) =
                __floats2half2_rn(acc[nn][0] * da, acc[nn][1] * da);
        if (rb < NN)
            *reinterpret_cast<__half2*>(&g_h2p[(size_t)rb * FOUT + col]) =
                __floats2half2_rn(acc[nn][2] * db, acc[nn][3] * db);
    }
}

// ---------------- AGG 2: out[i] = dinv[i]*(sum_nb h2p + h2p[i]) + b2 ----------------
__global__ void __launch_bounds__(256) k_agg2(const float* __restrict__ b2,
                                              float* __restrict__ out) {
    int gw   = (blockIdx.x * 256 + threadIdx.x) >> 5;
    int lane = threadIdx.x & 31;
    if (gw >= NN) return;
    const __half2* h = reinterpret_cast<const __half2*>(g_h2p);
    float2 acc = __half22float2(h[(size_t)gw * 32 + lane]);   // self-loop
    int s0 = g_rowptr[gw], s1 = g_rowptr[gw + 1];
    int j = s0;
    for (; j + 1 < s1; j += 2) {
        int sA = __ldg(&g_col[j]);
        int sB = __ldg(&g_col[j + 1]);
        float2 a = __half22float2(__ldg(&h[(size_t)sA * 32 + lane]));
        float2 b = __half22float2(__ldg(&h[(size_t)sB * 32 + lane]));
        acc.x += a.x + b.x;
        acc.y += a.y + b.y;
    }
    if (j < s1) {
        int sA = __ldg(&g_col[j]);
        float2 a = __half22float2(__ldg(&h[(size_t)sA * 32 + lane]));
        acc.x += a.x; acc.y += a.y;
    }
    float dv = g_dinv[gw];
    float2 bb = reinterpret_cast<const float2*>(b2)[lane];
    float2 z;
    z.x = acc.x * dv + bb.x;
    z.y = acc.y * dv + bb.y;
    reinterpret_cast<float2*>(out)[(size_t)gw * 32 + lane] = z;
}

// ---------------- launch ----------------
extern "C" void kernel_launch(void* const* d_in, const int* in_sizes, int n_in,
                              void* d_out, int out_size) {
    const float* x  = (const float*)d_in[0];
    const int*   ei = (const int*)d_in[1];
    const float* W1 = (const float*)d_in[2];
    const float* b1 = (const float*)d_in[3];
    const float* W2 = (const float*)d_in[4];
    const float* b2 = (const float*)d_in[5];
    float* out = (float*)d_out;

    k_init <<<(NN + 255) / 256, 256>>>();
    k_count<<<(NE / 2 + 255) / 256, 256>>>(ei);
    k_scan <<<1, 1024>>>();
    k_fill <<<(NE / 2 + 255) / 256, 256>>>(ei);
    k_convW<<<(FIN * FHID + FHID * FOUT + 255) / 256, 256>>>(W1, W2);
    k_gemm1<<<(NN + 63) / 64, 256>>>(x);
    k_agg1 <<<(NN * 32 + 255) / 256, 256>>>(b1);
    k_gemm2<<<(NN + 63) / 64, 256>>>();
    k_agg2 <<<(NN * 32 + 255) / 256, 256>>>(b2, out);
}